// round 10
// baseline (speedup 1.0000x reference)
#include <cuda_runtime.h>
#include <cuda_fp16.h>
#include <cstdint>

// out[b,n,f] = sum_m A[b,n,m] * X[b,m,f] + bias[f]
// A: [8,4096,4096] fp32, X: [8,4096,64] fp32, bias [64].
//
// R5 data path (fp16 mma.sync, register-staged double buffer, KC=64) at
// OCCUPANCY 3: smaller per-CTA tile (4-5 sixteen-row groups, pa[5]) to fit
// 85 regs/thread and 36KB smem/CTA. Grid 444 = 3*148 exact; batches 0-3 ->
// 55 CTAs, batches 4-7 -> 56 CTAs (batch-aligned, ~1.7% imbalance). 24
// warps/SM smooth the LDG bursts that capped DRAM at 73% with 16 warps.

#define NBATCH  8
#define NN      4096
#define FF      64
#define KC      64
#define NCH     (NN / KC)       // 64
#define MAXG    5

#define AST     (MAXG * 16 * 128)   // 10240 B: 80 rows x 64 fp16
#define BST     (FF * 128)          // 8192 B
#define STB     (AST + BST)         // 18432
#define SMEM_DYN (2 * STB)          // 36864

__device__ __half g_Xt[NBATCH * FF * NN];   // [b][f][k] fp16

__device__ __forceinline__ uint32_t smem_u32(const void* p) {
    uint32_t a;
    asm("{ .reg .u64 t; cvta.to.shared.u64 t, %1; cvt.u32.u64 %0, t; }"
        : "=r"(a) : "l"(p));
    return a;
}
#define SW(o) ((o) ^ (((o) >> 3) & 0x70))

// ---------- prep: Xt[b][f][k] = fp16(X[b][k][f]) ----------
__global__ __launch_bounds__(256) void prep_xt_kernel(const float* __restrict__ X) {
    __shared__ float t[32][FF + 1];
    const int b  = blockIdx.y;
    const int k0 = blockIdx.x * 32;
    const int tx = threadIdx.x;
    const int ty = threadIdx.y;
#pragma unroll
    for (int i = 0; i < 4; ++i) {
        const int r = ty + 8 * i;
        const float* src = X + ((size_t)b * NN + k0 + r) * FF;
        t[r][tx]      = src[tx];
        t[r][tx + 32] = src[tx + 32];
    }
    __syncthreads();
#pragma unroll
    for (int j = 0; j < 8; ++j) {
        const int f = ty + 8 * j;
        g_Xt[((size_t)b * FF + f) * NN + k0 + tx] = __float2half_rn(t[tx][f]);
    }
}

// ---------- main GEMM ----------
__global__ __launch_bounds__(256, 3) void gemm_f16_occ3(
    const float* __restrict__ A,
    const float* __restrict__ bias,
    float* __restrict__ out)
{
    extern __shared__ char ds[];
    const uint32_t sb = smem_u32(ds);

    const int tid  = threadIdx.x;
    const int wid  = tid >> 5;
    const int lane = tid & 31;

    // batch-aligned uneven grid: batches 0-3: 55 CTAs, 4-7: 56 CTAs
    int b, ct, CB;
    {
        const int x = blockIdx.x;
        if (x < 220) { b = x / 55;        ct = x % 55;        CB = 55; }
        else         { b = 4 + (x - 220) / 56; ct = (x - 220) % 56; CB = 56; }
    }
    const int g0 = (ct * 256) / CB;
    const int g1 = ((ct + 1) * 256) / CB;
    const int NG = g1 - g0;             // 4 or 5 (16-row groups)
    const int nrows = NG * 16;

    const float*  Ab = A + ((size_t)b * NN + (size_t)g0 * 16) * NN;
    const __half* Xb = g_Xt + (size_t)b * FF * NN;

    // producer addressing (constant per thread)
    const int arow = tid >> 4;
    const int ac4  = tid & 15;
    const int brow = tid >> 3;
    const int bc   = tid & 7;
    const float*  a_ld = Ab + (size_t)arow * NN + ac4 * 4;
    const __half* b_ld = Xb + (size_t)brow * NN + bc * 8;
    const uint32_t a_sts = SW((uint32_t)(arow * 128 + ac4 * 8));
    const uint32_t b_sts = SW((uint32_t)(brow * 128 + bc * 16));

    // ldmatrix lane decomposition
    const int li = lane >> 3;
    const int lr = lane & 7;
    const uint32_t a_off =
        (uint32_t)((wid * 16 + (li & 1) * 8 + lr) * 128 + (li >> 1) * 16);
    const uint32_t b_off =
        (uint32_t)(((li >> 1) * 8 + lr) * 128 + (li & 1) * 16);

    float acc[8][4];
#pragma unroll
    for (int n = 0; n < 8; ++n)
#pragma unroll
        for (int j = 0; j < 4; ++j) acc[n][j] = 0.0f;

    float4 pa[MAXG];
    uint4  pb[2];

    auto ldg_chunk = [&](int c) {
        const size_t ko = (size_t)c * KC;
#pragma unroll
        for (int i = 0; i < MAXG; ++i)
            if (16 * i < nrows)
                pa[i] = *reinterpret_cast<const float4*>(
                    a_ld + (size_t)(16 * i) * NN + ko);
#pragma unroll
        for (int i = 0; i < 2; ++i)
            pb[i] = *reinterpret_cast<const uint4*>(
                b_ld + (size_t)(32 * i) * NN + ko);
    };
    auto sts_chunk = [&](uint32_t abase, uint32_t bbase) {
#pragma unroll
        for (int i = 0; i < MAXG; ++i)
            if (16 * i < nrows) {
                __half2 h0 = __floats2half2_rn(pa[i].x, pa[i].y);
                __half2 h1 = __floats2half2_rn(pa[i].z, pa[i].w);
                asm volatile("st.shared.v2.b32 [%0], {%1, %2};"
                             :: "r"(abase + a_sts + (uint32_t)i * 2048),
                                "r"(*(uint32_t*)&h0), "r"(*(uint32_t*)&h1)
                             : "memory");
            }
#pragma unroll
        for (int i = 0; i < 2; ++i)
            asm volatile("st.shared.v4.b32 [%0], {%1,%2,%3,%4};"
                         :: "r"(bbase + b_sts + (uint32_t)i * 4096),
                            "r"(pb[i].x), "r"(pb[i].y), "r"(pb[i].z), "r"(pb[i].w)
                         : "memory");
    };

    // ---- prologue: load + stage chunk 0 ----
    ldg_chunk(0);
    sts_chunk(sb, sb + AST);
    __syncthreads();

    for (int c = 0; c < NCH; ++c) {
        // prefetch next chunk into registers
        if (c + 1 < NCH) ldg_chunk(c + 1);

        // compute chunk c from stage (c&1)
        if (wid < NG) {
            const uint32_t as = sb + (uint32_t)(c & 1) * STB;
            const uint32_t bs = as + AST;
#pragma unroll
            for (int ks = 0; ks < 4; ++ks) {
                uint32_t a0, a1, a2, a3;
                asm volatile(
                    "ldmatrix.sync.aligned.m8n8.x4.shared.b16 {%0,%1,%2,%3}, [%4];"
                    : "=r"(a0), "=r"(a1), "=r"(a2), "=r"(a3)
                    : "r"(as + SW(a_off + (uint32_t)ks * 32)));
#pragma unroll
                for (int p = 0; p < 4; ++p) {
                    uint32_t b0, b1, b2, b3;
                    asm volatile(
                        "ldmatrix.sync.aligned.m8n8.x4.shared.b16 {%0,%1,%2,%3}, [%4];"
                        : "=r"(b0), "=r"(b1), "=r"(b2), "=r"(b3)
                        : "r"(bs + SW(b_off + (uint32_t)p * 2048 + (uint32_t)ks * 32)));
                    asm volatile(
                        "mma.sync.aligned.m16n8k16.row.col.f32.f16.f16.f32 "
                        "{%0,%1,%2,%3}, {%4,%5,%6,%7}, {%8,%9}, {%0,%1,%2,%3};"
                        : "+f"(acc[2*p][0]), "+f"(acc[2*p][1]),
                          "+f"(acc[2*p][2]), "+f"(acc[2*p][3])
                        : "r"(a0), "r"(a1), "r"(a2), "r"(a3), "r"(b0), "r"(b1));
                    asm volatile(
                        "mma.sync.aligned.m16n8k16.row.col.f32.f16.f16.f32 "
                        "{%0,%1,%2,%3}, {%4,%5,%6,%7}, {%8,%9}, {%0,%1,%2,%3};"
                        : "+f"(acc[2*p+1][0]), "+f"(acc[2*p+1][1]),
                          "+f"(acc[2*p+1][2]), "+f"(acc[2*p+1][3])
                        : "r"(a0), "r"(a1), "r"(a2), "r"(a3), "r"(b2), "r"(b3));
                }
            }
        }

        // stage chunk c+1 into the other buffer
        if (c + 1 < NCH) {
            const uint32_t as2 = sb + (uint32_t)((c + 1) & 1) * STB;
            sts_chunk(as2, as2 + AST);
        }
        __syncthreads();
    }

    // ---- epilogue: add bias, store ----
    if (wid < NG) {
        const int g = lane >> 2, q = lane & 3;
        const int mlo = (g0 + wid) * 16 + g;
        float* o0 = out + ((size_t)b * NN + mlo) * FF;
        float* o1 = o0 + (size_t)8 * FF;
#pragma unroll
        for (int nt = 0; nt < 8; ++nt) {
            const int col = nt * 8 + q * 2;
            const float2 bv = *reinterpret_cast<const float2*>(bias + col);
            float2 v0 = make_float2(acc[nt][0] + bv.x, acc[nt][1] + bv.y);
            float2 v1 = make_float2(acc[nt][2] + bv.x, acc[nt][3] + bv.y);
            *reinterpret_cast<float2*>(o0 + col) = v0;
            *reinterpret_cast<float2*>(o1 + col) = v1;
        }
    }
}

extern "C" void kernel_launch(void* const* d_in, const int* in_sizes, int n_in,
                              void* d_out, int out_size)
{
    const float* A    = (const float*)d_in[0]; // adjacent [8,4096,4096]
    const float* X    = (const float*)d_in[1]; // annotations [8,4096,64]
    const float* bias = (const float*)d_in[2]; // bias [1,1,64]
    float* out = (float*)d_out;

    cudaFuncSetAttribute(gemm_f16_occ3,
                         cudaFuncAttributeMaxDynamicSharedMemorySize, SMEM_DYN);

    dim3 pg(NN / 32, NBATCH);
    dim3 pbk(32, 8);
    prep_xt_kernel<<<pg, pbk>>>(X);

    gemm_f16_occ3<<<444, 256, SMEM_DYN>>>(A, bias, out);
}

// round 11
// speedup vs baseline: 1.0716x; 1.0716x over previous
#include <cuda_runtime.h>
#include <cuda_fp16.h>
#include <cstdint>

// out[b,n,f] = sum_m A[b,n,m] * X[b,m,f] + bias[f]
// A: [8,4096,4096] fp32, X: [8,4096,64] fp32, bias [64].
//
// SINGLE-LAUNCH version of R9 (best GEMM: 93.6us): the Xt transpose/convert
// prep is folded into the GEMM kernel preamble, separated by a software
// global barrier. Grid = 296 = 2 CTAs/SM exactly one wave -> all CTAs
// co-resident, so an epoch-based atomic counter barrier is safe (each graph
// replay advances the counter by exactly 296). A-sub0 LDGs are issued while
// spinning on the barrier. GEMM main loop is R9 verbatim (2 KC=64 sub-chunks
// per iteration, register-staged double buffer, 16-row balanced split).

#define NBATCH  8
#define NN      4096
#define FF      64
#define CTAS_B  37
#define GRID    (NBATCH * CTAS_B)   // 296
#define MAXG    7
#define NSUB    64                  // KC=64 sub-chunks
#define NIT     32                  // 2 sub-chunks per iteration

#define SUB_A   14336               // 112 rows x 128B fp16
#define SUB_B   8192                // 64 f-rows x 128B fp16
#define STB2    (2 * (SUB_A + SUB_B))   // 45056 per stage
#define OFF_B   (2 * SUB_A)             // 28672 within stage
#define SMEM_DYN (2 * STB2)             // 90112

__device__ __half g_Xt[NBATCH * FF * NN];   // [b][f][k] fp16
__device__ unsigned g_bar = 0;              // monotonic epoch barrier counter

__device__ __forceinline__ uint32_t smem_u32(const void* p) {
    uint32_t a;
    asm("{ .reg .u64 t; cvta.to.shared.u64 t, %1; cvt.u32.u64 %0, t; }"
        : "=r"(a) : "l"(p));
    return a;
}
#define SW(o) ((o) ^ (((o) >> 3) & 0x70))

__global__ __launch_bounds__(256, 2) void gemm_f16_fused1(
    const float* __restrict__ A,
    const float* __restrict__ X,
    const float* __restrict__ bias,
    float* __restrict__ out)
{
    extern __shared__ char ds[];
    const uint32_t sb = smem_u32(ds);

    const int tid  = threadIdx.x;
    const int wid  = tid >> 5;
    const int lane = tid & 31;

    // ================= phase 1: convert X -> g_Xt (my slab share) ==========
    // 1024 slabs (b in 0..7, k0 in 0..127*32), each 32k x 64f, smem transpose.
    {
        float* tt = reinterpret_cast<float*>(ds);     // [32][65]
        const int tx = tid & 31;
        const int ty = tid >> 5;
        const int s0 = (blockIdx.x * 1024) / GRID;
        const int s1 = ((blockIdx.x + 1) * 1024) / GRID;
        for (int s = s0; s < s1; ++s) {
            const int cb = s >> 7;
            const int k0 = (s & 127) * 32;
#pragma unroll
            for (int i = 0; i < 4; ++i) {
                const int r = ty + 8 * i;
                const float* src = X + ((size_t)cb * NN + k0 + r) * FF;
                tt[r * 65 + tx]      = src[tx];
                tt[r * 65 + tx + 32] = src[tx + 32];
            }
            __syncthreads();
#pragma unroll
            for (int j = 0; j < 8; ++j) {
                const int f = ty + 8 * j;
                g_Xt[((size_t)cb * FF + f) * NN + k0 + tx] =
                    __float2half_rn(tt[tx * 65 + f]);
            }
            __syncthreads();
        }
    }

    // ---- arrive at global barrier (release) ----
    __threadfence();
    __syncthreads();
    unsigned bar_target = 0;
    if (tid == 0) {
        const unsigned my = atomicAdd(&g_bar, 1u);
        bar_target = my - (my % (unsigned)GRID) + (unsigned)GRID;
    }

    // ================= phase 2: GEMM (R9 verbatim) =========================
    const int b  = blockIdx.x / CTAS_B;
    const int ct = blockIdx.x % CTAS_B;
    const int g0 = (ct * 256) / CTAS_B;
    const int g1 = ((ct + 1) * 256) / CTAS_B;
    const int NG = g1 - g0;             // 6 or 7 (16-row groups)
    const int nrows = NG * 16;

    const float*  Ab = A + ((size_t)b * NN + (size_t)g0 * 16) * NN;
    const __half* Xb = g_Xt + (size_t)b * FF * NN;

    const int arow = tid >> 4;
    const int ac4  = tid & 15;
    const int brow = tid >> 3;
    const int bc   = tid & 7;
    const float*  a_ld = Ab + (size_t)arow * NN + ac4 * 4;
    const __half* b_ld = Xb + (size_t)brow * NN + bc * 8;
    const uint32_t a_sts = SW((uint32_t)(arow * 128 + ac4 * 8));
    const uint32_t b_sts = SW((uint32_t)(brow * 128 + bc * 16));

    const int li = lane >> 3;
    const int lr = lane & 7;
    const uint32_t a_off =
        (uint32_t)((wid * 16 + (li & 1) * 8 + lr) * 128 + (li >> 1) * 16);
    const uint32_t b_off =
        (uint32_t)(((li >> 1) * 8 + lr) * 128 + (li & 1) * 16);

    float acc[8][4];
#pragma unroll
    for (int n = 0; n < 8; ++n)
#pragma unroll
        for (int j = 0; j < 4; ++j) acc[n][j] = 0.0f;

    float4 pa[MAXG];
    uint4  pb[2];

    auto ldg_a = [&](int s) {
        const size_t ko = (size_t)s * 64;
#pragma unroll
        for (int i = 0; i < MAXG; ++i)
            if (16 * i < nrows)
                pa[i] = *reinterpret_cast<const float4*>(
                    a_ld + (size_t)(16 * i) * NN + ko);
    };
    auto ldg_b = [&](int s) {
        const size_t ko = (size_t)s * 64;
#pragma unroll
        for (int i = 0; i < 2; ++i)
            pb[i] = *reinterpret_cast<const uint4*>(
                b_ld + (size_t)(32 * i) * NN + ko);
    };
    auto sts_sub = [&](uint32_t abase, uint32_t bbase) {
#pragma unroll
        for (int i = 0; i < MAXG; ++i)
            if (16 * i < nrows) {
                __half2 h0 = __floats2half2_rn(pa[i].x, pa[i].y);
                __half2 h1 = __floats2half2_rn(pa[i].z, pa[i].w);
                asm volatile("st.shared.v2.b32 [%0], {%1, %2};"
                             :: "r"(abase + a_sts + (uint32_t)i * 2048),
                                "r"(*(uint32_t*)&h0), "r"(*(uint32_t*)&h1)
                             : "memory");
            }
#pragma unroll
        for (int i = 0; i < 2; ++i)
            asm volatile("st.shared.v4.b32 [%0], {%1,%2,%3,%4};"
                         :: "r"(bbase + b_sts + (uint32_t)i * 4096),
                            "r"(pb[i].x), "r"(pb[i].y), "r"(pb[i].z), "r"(pb[i].w)
                         : "memory");
    };
    auto compute_sub = [&](uint32_t abase, uint32_t bbase) {
#pragma unroll
        for (int ks = 0; ks < 4; ++ks) {
            uint32_t a0, a1, a2, a3;
            asm volatile(
                "ldmatrix.sync.aligned.m8n8.x4.shared.b16 {%0,%1,%2,%3}, [%4];"
                : "=r"(a0), "=r"(a1), "=r"(a2), "=r"(a3)
                : "r"(abase + SW(a_off + (uint32_t)ks * 32)));
#pragma unroll
            for (int p = 0; p < 4; ++p) {
                uint32_t b0, b1, b2, b3;
                asm volatile(
                    "ldmatrix.sync.aligned.m8n8.x4.shared.b16 {%0,%1,%2,%3}, [%4];"
                    : "=r"(b0), "=r"(b1), "=r"(b2), "=r"(b3)
                    : "r"(bbase + SW(b_off + (uint32_t)p * 2048 + (uint32_t)ks * 32)));
                asm volatile(
                    "mma.sync.aligned.m16n8k16.row.col.f32.f16.f16.f32 "
                    "{%0,%1,%2,%3}, {%4,%5,%6,%7}, {%8,%9}, {%0,%1,%2,%3};"
                    : "+f"(acc[2*p][0]), "+f"(acc[2*p][1]),
                      "+f"(acc[2*p][2]), "+f"(acc[2*p][3])
                    : "r"(a0), "r"(a1), "r"(a2), "r"(a3), "r"(b0), "r"(b1));
                asm volatile(
                    "mma.sync.aligned.m16n8k16.row.col.f32.f16.f16.f32 "
                    "{%0,%1,%2,%3}, {%4,%5,%6,%7}, {%8,%9}, {%0,%1,%2,%3};"
                    : "+f"(acc[2*p+1][0]), "+f"(acc[2*p+1][1]),
                      "+f"(acc[2*p+1][2]), "+f"(acc[2*p+1][3])
                    : "r"(a0), "r"(a1), "r"(a2), "r"(a3), "r"(b2), "r"(b3));
            }
        }
    };

    // A sub0 does not depend on g_Xt: issue its LDGs while spinning.
    ldg_a(0);

    // ---- wait at global barrier (acquire) ----
    if (tid == 0) {
        unsigned v;
        do {
            asm volatile("ld.acquire.gpu.global.u32 %0, [%1];"
                         : "=r"(v) : "l"(&g_bar));
            if (v >= bar_target) break;
            __nanosleep(32);
        } while (true);
    }
    __syncthreads();

    // ---- prologue: fill buffer 0 (subs 0,1), preload sub 2 ----
    ldg_b(0);
    sts_sub(sb,         sb + OFF_B);
    ldg_a(1); ldg_b(1);
    sts_sub(sb + SUB_A, sb + OFF_B + SUB_B);
    ldg_a(2); ldg_b(2);
    __syncthreads();

    for (int C = 0; C < NIT; ++C) {
        const uint32_t cur = sb + (uint32_t)(C & 1) * STB2;
        const uint32_t nxt = sb + (uint32_t)((C + 1) & 1) * STB2;

        if (2 * C + 2 < NSUB) sts_sub(nxt, nxt + OFF_B);
        if (2 * C + 3 < NSUB) { ldg_a(2 * C + 3); ldg_b(2 * C + 3); }

        if (wid < NG) compute_sub(cur, cur + OFF_B);                 // sub 2C

        if (2 * C + 3 < NSUB) sts_sub(nxt + SUB_A, nxt + OFF_B + SUB_B);
        if (2 * C + 4 < NSUB) { ldg_a(2 * C + 4); ldg_b(2 * C + 4); }

        if (wid < NG) compute_sub(cur + SUB_A, cur + OFF_B + SUB_B); // sub 2C+1

        __syncthreads();
    }

    // ---- epilogue: add bias, store ----
    if (wid < NG) {
        const int g = lane >> 2, q = lane & 3;
        const int mlo = (g0 + wid) * 16 + g;
        float* o0 = out + ((size_t)b * NN + mlo) * FF;
        float* o1 = o0 + (size_t)8 * FF;
#pragma unroll
        for (int nt = 0; nt < 8; ++nt) {
            const int col = nt * 8 + q * 2;
            const float2 bv = *reinterpret_cast<const float2*>(bias + col);
            float2 v0 = make_float2(acc[nt][0] + bv.x, acc[nt][1] + bv.y);
            float2 v1 = make_float2(acc[nt][2] + bv.x, acc[nt][3] + bv.y);
            *reinterpret_cast<float2*>(o0 + col) = v0;
            *reinterpret_cast<float2*>(o1 + col) = v1;
        }
    }
}

extern "C" void kernel_launch(void* const* d_in, const int* in_sizes, int n_in,
                              void* d_out, int out_size)
{
    const float* A    = (const float*)d_in[0]; // adjacent [8,4096,4096]
    const float* X    = (const float*)d_in[1]; // annotations [8,4096,64]
    const float* bias = (const float*)d_in[2]; // bias [1,1,64]
    float* out = (float*)d_out;

    cudaFuncSetAttribute(gemm_f16_fused1,
                         cudaFuncAttributeMaxDynamicSharedMemorySize, SMEM_DYN);

    gemm_f16_fused1<<<GRID, 256, SMEM_DYN>>>(A, X, bias, out);
}